// round 2
// baseline (speedup 1.0000x reference)
#include <cuda_runtime.h>
#include <stdint.h>

// out[i] = -cost[i, inputs[i]] * mask[i]
// cost: float32 [N, V]; inputs: int32 OR int64 [N] (detected at runtime);
// mask: float32 [N]; out: float32 [N]. N=16384, V=32000.

__device__ int g_idx_is_i32;  // 1 => indices are int32, 0 => int64

// Detect index dtype by inspecting the first N int32 words of the buffer.
// int64 little-endian layout of values < 2^31 has ALL odd words == 0.
// int32 layout of random indices has nonzero odd words w.p. ~1.
__global__ void detect_idx_dtype(const int* __restrict__ idx32, int n) {
    __shared__ int s_or[256];
    int acc = 0;
    // Only touch words [0, n) — safe for both layouts.
    for (int j = 2 * threadIdx.x + 1; j < n; j += 2 * blockDim.x)
        acc |= idx32[j];
    s_or[threadIdx.x] = acc;
    __syncthreads();
    for (int s = blockDim.x / 2; s > 0; s >>= 1) {
        if (threadIdx.x < s) s_or[threadIdx.x] |= s_or[threadIdx.x + s];
        __syncthreads();
    }
    if (threadIdx.x == 0) g_idx_is_i32 = (s_or[0] != 0) ? 1 : 0;
}

__global__ void masked_nll_kernel(const float* __restrict__ cost,
                                  const int* __restrict__ idx32,
                                  const float* __restrict__ mask,
                                  float* __restrict__ out,
                                  int n, long long v) {
    int i = blockIdx.x * blockDim.x + threadIdx.x;
    if (i >= n) return;
    // Uniform branch: flag is the same for every thread.
    long long idx;
    if (g_idx_is_i32) {
        idx = (long long)idx32[i];
    } else {
        // int64 little-endian, value < 2^31: low word carries the index.
        idx = (long long)idx32[2 * i];
    }
    float picked = __ldg(&cost[(long long)i * v + idx]);
    out[i] = -picked * mask[i];
}

extern "C" void kernel_launch(void* const* d_in, const int* in_sizes, int n_in,
                              void* d_out, int out_size) {
    const float* cost  = (const float*)d_in[0];
    const int*   idx32 = (const int*)d_in[1];
    const float* mask  = (const float*)d_in[2];
    float*       out   = (float*)d_out;

    int n = in_sizes[1];                       // N = element count of inputs[]
    long long v = (long long)in_sizes[0] / n;  // V = cost elems / N

    detect_idx_dtype<<<1, 256>>>(idx32, n);

    int threads = 256;
    int blocks = (n + threads - 1) / threads;
    masked_nll_kernel<<<blocks, threads>>>(cost, idx32, mask, out, n, v);
}

// round 3
// speedup vs baseline: 1.9231x; 1.9231x over previous
#include <cuda_runtime.h>
#include <stdint.h>

// out[i] = -cost[i, inputs[i]] * mask[i]
// cost: float32 [N, V]; inputs: int32 OR int64 [N] (warp-level runtime detect);
// mask: float32 [N]; out: float32 [N]. N=16384, V=32000.
//
// Index-dtype detection, fused: interpret the index buffer as int32 words.
// An int64 little-endian layout of values < 2^31 has ALL odd words == 0.
// An int32 layout of random indices in [0,32000) has a nonzero odd word among
// the first 32 with overwhelming probability. Each warp checks the SAME first
// 32 odd words (L1-hot after the first warp) -> warp-uniform flag, no sync.

__global__ void masked_nll_fused(const float* __restrict__ cost,
                                 const int* __restrict__ idx32,
                                 const float* __restrict__ mask,
                                 float* __restrict__ out,
                                 int n, long long v) {
    int lane = threadIdx.x & 31;

    // Words 1,3,...,63 are within the first 32 elements of either layout
    // (n = 16384 >> 64 int32 words). Same addresses for every warp.
    int probe = idx32[2 * lane + 1];
    unsigned is_i32 = __reduce_or_sync(0xffffffffu, (unsigned)probe);

    int i = blockIdx.x * blockDim.x + threadIdx.x;
    if (i >= n) return;

    long long idx = is_i32 ? (long long)idx32[i]
                           : (long long)idx32[2 * i];  // low word of int64

    float picked = __ldg(&cost[(long long)i * v + idx]);
    out[i] = -picked * mask[i];
}

extern "C" void kernel_launch(void* const* d_in, const int* in_sizes, int n_in,
                              void* d_out, int out_size) {
    const float* cost  = (const float*)d_in[0];
    const int*   idx32 = (const int*)d_in[1];
    const float* mask  = (const float*)d_in[2];
    float*       out   = (float*)d_out;

    int n = in_sizes[1];                       // N = element count of inputs[]
    long long v = (long long)in_sizes[0] / n;  // V = cost elems / N

    int threads = 128;                         // 128 CTAs -> ~all 148 SMs
    int blocks = (n + threads - 1) / threads;
    masked_nll_fused<<<blocks, threads>>>(cost, idx32, mask, out, n, v);
}

// round 4
// speedup vs baseline: 1.9608x; 1.0196x over previous
#include <cuda_runtime.h>
#include <stdint.h>

// out[i] = -cost[i, inputs[i]] * mask[i]
// cost: float32 [N, V], inputs: int32 [N], mask: float32 [N], out: float32 [N]
// N = 16384, V = 32000.
//
// Index dtype is int32 — established empirically: a kernel reading the index
// buffer as int64 (2*N*4 bytes) faulted with an illegal memory access, which
// is only possible if the buffer is N*4 bytes. The reference's jnp.int64 is
// demoted to int32 by JAX's default x64-disabled config.
//
// Critical path per thread: idx load (DRAM) -> gather (DRAM). Two serialized
// round trips; everything else is coalesced and overlapped. 16384 threads in
// 128 CTAs spread the scattered gathers across ~all 148 SMs' LSU/L1tex queues.

__global__ void masked_nll_kernel(const float* __restrict__ cost,
                                  const int* __restrict__ idx,
                                  const float* __restrict__ mask,
                                  float* __restrict__ out,
                                  int n, unsigned v) {
    unsigned i = blockIdx.x * blockDim.x + threadIdx.x;
    if (i >= (unsigned)n) return;
    // Element offset fits in 32 bits: 16384*32000 + 31999 < 2^31.
    unsigned off = i * v + (unsigned)idx[i];
    float picked = __ldg(cost + off);
    out[i] = -picked * mask[i];
}

extern "C" void kernel_launch(void* const* d_in, const int* in_sizes, int n_in,
                              void* d_out, int out_size) {
    const float* cost = (const float*)d_in[0];
    const int*   idx  = (const int*)d_in[1];
    const float* mask = (const float*)d_in[2];
    float*       out  = (float*)d_out;

    int n = in_sizes[1];                      // N = element count of inputs[]
    unsigned v = (unsigned)(in_sizes[0] / n); // V = cost elems / N

    int threads = 128;                        // 128 CTAs -> ~all 148 SMs
    int blocks = (n + threads - 1) / threads;
    masked_nll_kernel<<<blocks, threads>>>(cost, idx, mask, out, n, v);
}